// round 15
// baseline (speedup 1.0000x reference)
#include <cuda_runtime.h>
#include <cstdint>
#include <cstddef>

// Problem constants (fixed by the benchmark shapes)
#define N_QUERY 32768   // 1024 rays * 32 samples
#define N_LIDAR 8192
#define FDIM    128
#define THREADS 512
#define WARPS   (THREADS / 32)      // 16
#define QPW     7                   // queries per warp-pass
#define PASSES  2                   // 16 warps * 2 passes * 7 = 224 queries/block
#define QPB     (WARPS * QPW * PASSES)          // 224
#define NBLK    ((N_QUERY + QPB - 1) / QPB)     // 147 blocks -> one full wave
#define PAIRS   (N_LIDAR / 2)       // 4096 point-pairs
#define NITER   (PAIRS / 32)        // 128 iterations (one pair per lane)
#define TI      8                   // iterations per tile (512 points/tile)
#define NTILE   (NITER / TI)        // 16 tiles

using u64 = unsigned long long;

// ---- packed f32x2 helpers (sm_103a): bitwise-identical per-half to scalar rn ----
__device__ __forceinline__ u64 pack2(float lo, float hi) {
    u64 r; asm("mov.b64 %0, {%1, %2};" : "=l"(r) : "f"(lo), "f"(hi)); return r;
}
__device__ __forceinline__ u64 dup2(float x) {
    u64 r; asm("mov.b64 %0, {%1, %1};" : "=l"(r) : "f"(x)); return r;
}
__device__ __forceinline__ u64 mul2(u64 a, u64 b) {
    u64 d; asm("mul.rn.f32x2 %0, %1, %2;" : "=l"(d) : "l"(a), "l"(b)); return d;
}
__device__ __forceinline__ u64 fma2(u64 a, u64 b, u64 c) {
    u64 d; asm("fma.rn.f32x2 %0, %1, %2, %3;" : "=l"(d) : "l"(a), "l"(b), "l"(c)); return d;
}
__device__ __forceinline__ u64 add2(u64 a, u64 b) {
    u64 d; asm("add.rn.f32x2 %0, %1, %2;" : "=l"(d) : "l"(a), "l"(b)); return d;
}
__device__ __forceinline__ float2 asf2(u64 v) {
    float2 f; asm("mov.b64 {%0, %1}, %2;" : "=f"(f.x), "=f"(f.y) : "l"(v)); return f;
}

// Monotone map: float order -> unsigned order (valid for ALL floats incl. negatives).
// Used ONLY for comparisons; never fed back into arithmetic.
__device__ __forceinline__ unsigned ford(float v) {
    unsigned b = __float_as_uint(v);
    return (b & 0x80000000u) ? ~b : (b | 0x80000000u);
}
__device__ __forceinline__ float funord(unsigned o) {
    unsigned b = (o & 0x80000000u) ? (o & 0x7fffffffu) : ~o;
    return __uint_as_float(b);
}

__global__ void __launch_bounds__(THREADS, 1)
nn_gather_kernel(const float* __restrict__ pts,
                 const float* __restrict__ lidar,
                 const float* __restrict__ features,
                 float* __restrict__ out)
{
    // Pair-packed, PRE-SCALED lidar: for points 2j, 2j+1
    //   sA[j] = (-2*x0, -2*x1, -2*y0, -2*y1)
    //   sB[j] = (-2*z0, -2*z1,  s0,    s1 )   (s = ||k||^2, unscaled)
    // Scaling by -2 is exact; rn(-2u) = -2*rn(u), so the dot chain below produces
    // exactly -2*cross with the reference's rounding at every step.
    extern __shared__ float4 smem4[];
    float4* sA = smem4;                 // [PAIRS]
    float4* sB = smem4 + PAIRS;         // [PAIRS]
    __shared__ int sidx[QPB];

    const int tid  = threadIdx.x;
    const int lane = tid & 31;
    const int warp = tid >> 5;

    // Cooperative fill; ||k||^2 with stepwise rounding (x^2+y^2)+z^2 on UNSCALED values
    for (int j = tid; j < PAIRS; j += THREADS) {
        float x0 = lidar[6 * j + 0], y0 = lidar[6 * j + 1], z0 = lidar[6 * j + 2];
        float x1 = lidar[6 * j + 3], y1 = lidar[6 * j + 4], z1 = lidar[6 * j + 5];
        float s0 = __fadd_rn(__fadd_rn(__fmul_rn(x0, x0), __fmul_rn(y0, y0)),
                             __fmul_rn(z0, z0));
        float s1 = __fadd_rn(__fadd_rn(__fmul_rn(x1, x1), __fmul_rn(y1, y1)),
                             __fmul_rn(z1, z1));
        sA[j] = make_float4(-2.0f * x0, -2.0f * x1, -2.0f * y0, -2.0f * y1);
        sB[j] = make_float4(-2.0f * z0, -2.0f * z1, s0, s1);
    }
    __syncthreads();

    const float INF = __int_as_float(0x7f800000);
    const int qbase = blockIdx.x * QPB;             // global query base of block

    for (int pass = 0; pass < PASSES; pass++) {
        // This warp-pass owns QPW consecutive queries.
        const int ql0 = (pass * WARPS + warp) * QPW;    // block-local query base
        const int mg0 = qbase + ql0;                    // global query base

        // Duplicated packed query constants (dup2 once per pass — amortized).
        // Tail safety: clamp the load index; results for m >= N_QUERY discarded.
        u64 QXd[QPW], QYd[QPW], QZd[QPW], QSd[QPW];
        #pragma unroll
        for (int q = 0; q < QPW; q++) {
            const int m = min(mg0 + q, N_QUERY - 1);
            float ax = __ldg(pts + 3 * m + 0);
            float ay = __ldg(pts + 3 * m + 1);
            float az = __ldg(pts + 3 * m + 2);
            float as = __fadd_rn(__fadd_rn(__fmul_rn(ax, ax), __fmul_rn(ay, ay)),
                                 __fmul_rn(az, az));
            QXd[q] = dup2(ax); QYd[q] = dup2(ay);
            QZd[q] = dup2(az); QSd[q] = dup2(as);
        }

        float best[QPW];
        int   btile[QPW];
        float tmin[QPW];
        #pragma unroll
        for (int q = 0; q < QPW; q++) { best[q] = INF; btile[q] = 0; tmin[q] = INF; }

        // Software-pipelined scan: prefetch iter i+1's pair while computing iter i.
        // Lane handles pair i*32+lane (points 64i+2*lane, +1); tile = TI iters.
        const float4* pa = sA + lane;
        const float4* pb = sB + lane;
        float4 A = pa[0];
        float4 B = pb[0];

        for (int t = 0; t < NTILE; t++) {
            #pragma unroll
            for (int ii = 0; ii < TI; ii++) {
                const int i = t * TI + ii;
                // Prefetch next iteration (clamped dummy reload on the last iter).
                const int nx = (i + 1 < NITER) ? (i + 1) : i;
                const float4 An = pa[nx * 32];
                const float4 Bn = pb[nx * 32];

                const u64 KX = pack2(A.x, A.y);   // (-2x0, -2x1) — free reg pair
                const u64 KY = pack2(A.z, A.w);   // (-2y0, -2y1)
                const u64 KZ = pack2(B.x, B.y);   // (-2z0, -2z1)
                const u64 KS = pack2(B.z, B.w);   // ( s0,   s1 )

                #pragma unroll
                for (int q = 0; q < QPW; q++) {
                    // c' = fma(qz,-2kz, fma(qy,-2ky, rn(qx*-2kx))) == -2*cross, exact
                    u64 c = fma2(QZd[q], KZ, fma2(QYd[q], KY, mul2(QXd[q], KX)));
                    // d2 = rn( rn(qs + c') + ks ) == rn( rn(qs - 2*cross) + ks )
                    u64 d2 = add2(add2(QSd[q], c), KS);
                    float2 f = asf2(d2);          // free unpack
                    tmin[q] = fminf(tmin[q], fminf(f.x, f.y));
                }

                A = An; B = Bn;
            }

            #pragma unroll
            for (int q = 0; q < QPW; q++) {
                // strict < : keeps the FIRST tile where this lane's min appeared
                if (tmin[q] < best[q]) { best[q] = tmin[q]; btile[q] = t; }
                tmin[q] = INF;
            }
        }

        // Epilogue: per query -> fused (value, tile) u64 min-reduction, then
        // exact first-index recovery in the winning tile.
        for (int q = 0; q < QPW; q++) {
            // key = ord(best) << 32 | tile : min-key == min value, earliest tile on ties
            u64 key = ((u64)ford(best[q]) << 32) | (unsigned)btile[q];
            #pragma unroll
            for (int off = 16; off > 0; off >>= 1)
                key = min(key, (u64)__shfl_xor_sync(0xffffffffu, (unsigned long long)key, off));
            const float v = funord((unsigned)(key >> 32));
            const int   tl = (int)(unsigned)(key & 0xffffffffu);

            // Reload this query's scalars (uniform) and rescan the winning tile
            // with the same bit-exact sequence on the scaled inputs.
            const int m = min(mg0 + q, N_QUERY - 1);
            const float fqx = __ldg(pts + 3 * m + 0);
            const float fqy = __ldg(pts + 3 * m + 1);
            const float fqz = __ldg(pts + 3 * m + 2);
            const float fqs = __fadd_rn(__fadd_rn(__fmul_rn(fqx, fqx),
                                                  __fmul_rn(fqy, fqy)),
                                        __fmul_rn(fqz, fqz));
            int cand = 0x7fffffff;
            #pragma unroll
            for (int ii = 0; ii < TI; ii++) {
                const int j = (tl * TI + ii) * 32 + lane;   // pair index
                const float4 Ar = sA[j];
                const float4 Br = sB[j];
                float c0 = __fmaf_rn(fqz, Br.x,
                           __fmaf_rn(fqy, Ar.z, __fmul_rn(fqx, Ar.x)));
                float d0 = __fadd_rn(__fadd_rn(fqs, c0), Br.z);
                if (d0 == v) cand = min(cand, 2 * j);
                float c1 = __fmaf_rn(fqz, Br.y,
                           __fmaf_rn(fqy, Ar.w, __fmul_rn(fqx, Ar.y)));
                float d1 = __fadd_rn(__fadd_rn(fqs, c1), Br.w);
                if (d1 == v) cand = min(cand, 2 * j + 1);
            }
            #pragma unroll
            for (int off = 16; off > 0; off >>= 1)
                cand = min(cand, __shfl_xor_sync(0xffffffffu, cand, off));

            if (lane == 0 && (mg0 + q) < N_QUERY) sidx[ql0 + q] = cand;
        }
    }
    __syncthreads();

    // Warp-cooperative coalesced gather: one query row == 32 lanes x float4
    for (int qq = warp; qq < QPB; qq += WARPS) {
        const int m = qbase + qq;
        if (m >= N_QUERY) break;
        const int src = sidx[qq];
        const float4 v = *(const float4*)(features + (size_t)src * FDIM + lane * 4);
        *(float4*)(out + (size_t)m * FDIM + lane * 4) = v;
    }
}

extern "C" void kernel_launch(void* const* d_in, const int* in_sizes, int n_in,
                              void* d_out, int out_size) {
    const float* pts      = (const float*)d_in[0];  // (1, 1024, 32, 3)
    const float* lidar    = (const float*)d_in[1];  // (1, 8192, 3)
    const float* features = (const float*)d_in[2];  // (1, 8192, 128)
    float* out = (float*)d_out;                     // (1, 1024, 32, 128)

    const int smem_bytes = 2 * PAIRS * (int)sizeof(float4);   // 128 KB pair-packed
    cudaFuncSetAttribute(nn_gather_kernel,
                         cudaFuncAttributeMaxDynamicSharedMemorySize, smem_bytes);

    nn_gather_kernel<<<NBLK, THREADS, smem_bytes>>>(pts, lidar, features, out);
}

// round 16
// speedup vs baseline: 1.0005x; 1.0005x over previous
#include <cuda_runtime.h>
#include <cstdint>
#include <cstddef>

// Problem constants (fixed by the benchmark shapes)
#define N_QUERY 32768   // 1024 rays * 32 samples
#define N_LIDAR 8192
#define FDIM    128
#define THREADS 640
#define WARPS   (THREADS / 32)      // 20  (5 warps per SMSP)
#define QPW     4                   // queries per warp-pass
#define PASSES  3                   // 20 warps * 3 passes * 4 = 240 queries/block
#define QPB     (WARPS * QPW * PASSES)          // 240
#define NBLK    ((N_QUERY + QPB - 1) / QPB)     // 137 blocks -> one full wave
#define PAIRS   (N_LIDAR / 2)       // 4096 point-pairs
#define NITER   (PAIRS / 32)        // 128 iterations (one pair per lane)
#define TI      4                   // iterations per tile (256 points/tile)
#define NTILE   (NITER / TI)        // 32 tiles

using u64 = unsigned long long;

// ---- packed f32x2 helpers (sm_103a): bitwise-identical per-half to scalar rn ----
__device__ __forceinline__ u64 pack2(float lo, float hi) {
    u64 r; asm("mov.b64 %0, {%1, %2};" : "=l"(r) : "f"(lo), "f"(hi)); return r;
}
__device__ __forceinline__ u64 dup2(float x) {
    u64 r; asm("mov.b64 %0, {%1, %1};" : "=l"(r) : "f"(x)); return r;
}
__device__ __forceinline__ u64 mul2(u64 a, u64 b) {
    u64 d; asm("mul.rn.f32x2 %0, %1, %2;" : "=l"(d) : "l"(a), "l"(b)); return d;
}
__device__ __forceinline__ u64 fma2(u64 a, u64 b, u64 c) {
    u64 d; asm("fma.rn.f32x2 %0, %1, %2, %3;" : "=l"(d) : "l"(a), "l"(b), "l"(c)); return d;
}
__device__ __forceinline__ u64 add2(u64 a, u64 b) {
    u64 d; asm("add.rn.f32x2 %0, %1, %2;" : "=l"(d) : "l"(a), "l"(b)); return d;
}
__device__ __forceinline__ float2 asf2(u64 v) {
    float2 f; asm("mov.b64 {%0, %1}, %2;" : "=f"(f.x), "=f"(f.y) : "l"(v)); return f;
}

__global__ void __launch_bounds__(THREADS, 1)
nn_gather_kernel(const float* __restrict__ pts,
                 const float* __restrict__ lidar,
                 const float* __restrict__ features,
                 float* __restrict__ out)
{
    // Pair-packed, PRE-SCALED lidar: for points 2j, 2j+1
    //   sA[j] = (-2*x0, -2*x1, -2*y0, -2*y1)
    //   sB[j] = (-2*z0, -2*z1,  s0,    s1 )   (s = ||k||^2, unscaled)
    // Scaling by -2 is exact; rn(-2u) = -2*rn(u), so the dot chain below produces
    // exactly -2*cross with the reference's rounding at every step.
    extern __shared__ float4 smem4[];
    float4* sA = smem4;                 // [PAIRS]
    float4* sB = smem4 + PAIRS;         // [PAIRS]
    __shared__ int sidx[QPB];

    const int tid  = threadIdx.x;
    const int lane = tid & 31;
    const int warp = tid >> 5;

    // Cooperative fill; ||k||^2 with stepwise rounding (x^2+y^2)+z^2 on UNSCALED values
    for (int j = tid; j < PAIRS; j += THREADS) {
        float x0 = lidar[6 * j + 0], y0 = lidar[6 * j + 1], z0 = lidar[6 * j + 2];
        float x1 = lidar[6 * j + 3], y1 = lidar[6 * j + 4], z1 = lidar[6 * j + 5];
        float s0 = __fadd_rn(__fadd_rn(__fmul_rn(x0, x0), __fmul_rn(y0, y0)),
                             __fmul_rn(z0, z0));
        float s1 = __fadd_rn(__fadd_rn(__fmul_rn(x1, x1), __fmul_rn(y1, y1)),
                             __fmul_rn(z1, z1));
        sA[j] = make_float4(-2.0f * x0, -2.0f * x1, -2.0f * y0, -2.0f * y1);
        sB[j] = make_float4(-2.0f * z0, -2.0f * z1, s0, s1);
    }
    __syncthreads();

    const float INF = __int_as_float(0x7f800000);
    const int qbase = blockIdx.x * QPB;             // global query base of block

    for (int pass = 0; pass < PASSES; pass++) {
        // This warp-pass owns QPW consecutive queries.
        const int ql0 = (pass * WARPS + warp) * QPW;    // block-local query base
        const int mg0 = qbase + ql0;                    // global query base

        // Duplicated packed query constants (dup2 once per pass — amortized).
        // Tail safety: clamp the load index; results for m >= N_QUERY discarded.
        u64 QXd[QPW], QYd[QPW], QZd[QPW], QSd[QPW];
        #pragma unroll
        for (int q = 0; q < QPW; q++) {
            const int m = min(mg0 + q, N_QUERY - 1);
            float ax = __ldg(pts + 3 * m + 0);
            float ay = __ldg(pts + 3 * m + 1);
            float az = __ldg(pts + 3 * m + 2);
            float as = __fadd_rn(__fadd_rn(__fmul_rn(ax, ax), __fmul_rn(ay, ay)),
                                 __fmul_rn(az, az));
            QXd[q] = dup2(ax); QYd[q] = dup2(ay);
            QZd[q] = dup2(az); QSd[q] = dup2(as);
        }

        float best[QPW];
        int   btile[QPW];
        float tmin[QPW];
        #pragma unroll
        for (int q = 0; q < QPW; q++) { best[q] = INF; btile[q] = 0; tmin[q] = INF; }

        // Software-pipelined scan: prefetch iter i+1's pair while computing iter i.
        // Lane handles pair i*32+lane (points 64i+2*lane, +1); tile = 4 iters.
        float4 A = sA[lane];
        float4 B = sB[lane];

        #pragma unroll 4
        for (int i = 0; i < NITER; i++) {
            // Prefetch next iteration (clamped dummy reload on the last iter).
            const int nx = (i + 1 < NITER) ? (i + 1) : i;
            const float4 An = sA[nx * 32 + lane];
            const float4 Bn = sB[nx * 32 + lane];

            const u64 KX = pack2(A.x, A.y);       // (-2x0, -2x1) — free reg pair
            const u64 KY = pack2(A.z, A.w);       // (-2y0, -2y1)
            const u64 KZ = pack2(B.x, B.y);       // (-2z0, -2z1)
            const u64 KS = pack2(B.z, B.w);       // ( s0,   s1 )

            #pragma unroll
            for (int q = 0; q < QPW; q++) {
                // c' = fma(qz,-2kz, fma(qy,-2ky, rn(qx*-2kx))) == -2*cross, exact
                u64 c = fma2(QZd[q], KZ, fma2(QYd[q], KY, mul2(QXd[q], KX)));
                // d2 = rn( rn(qs + c') + ks )  == rn( rn(qs - 2*cross) + ks )
                u64 d2 = add2(add2(QSd[q], c), KS);
                float2 f = asf2(d2);              // free unpack
                tmin[q] = fminf(tmin[q], fminf(f.x, f.y));
            }

            if ((i & (TI - 1)) == TI - 1) {       // static under unroll 4
                const int t = i >> 2;
                #pragma unroll
                for (int q = 0; q < QPW; q++) {
                    // strict < : keeps the FIRST tile where this lane's min appeared
                    if (tmin[q] < best[q]) { best[q] = tmin[q]; btile[q] = t; }
                    tmin[q] = INF;
                }
            }

            A = An; B = Bn;
        }

        // Epilogue: per query -> warp min value, earliest tile, exact first index.
        for (int q = 0; q < QPW; q++) {
            float v = best[q];
            #pragma unroll
            for (int off = 16; off > 0; off >>= 1)
                v = fminf(v, __shfl_xor_sync(0xffffffffu, v, off));

            int tl = (best[q] == v) ? btile[q] : 0x7fffffff;
            #pragma unroll
            for (int off = 16; off > 0; off >>= 1)
                tl = min(tl, __shfl_xor_sync(0xffffffffu, tl, off));

            // Reload this query's scalars (uniform) and rescan the winning tile
            // with the same bit-exact sequence on the scaled inputs.
            const int m = min(mg0 + q, N_QUERY - 1);
            const float fqx = __ldg(pts + 3 * m + 0);
            const float fqy = __ldg(pts + 3 * m + 1);
            const float fqz = __ldg(pts + 3 * m + 2);
            const float fqs = __fadd_rn(__fadd_rn(__fmul_rn(fqx, fqx),
                                                  __fmul_rn(fqy, fqy)),
                                        __fmul_rn(fqz, fqz));
            int cand = 0x7fffffff;
            #pragma unroll
            for (int ii = 0; ii < TI; ii++) {
                const int j = (tl * TI + ii) * 32 + lane;   // pair index
                const float4 Ar = sA[j];
                const float4 Br = sB[j];
                float c0 = __fmaf_rn(fqz, Br.x,
                           __fmaf_rn(fqy, Ar.z, __fmul_rn(fqx, Ar.x)));
                float d0 = __fadd_rn(__fadd_rn(fqs, c0), Br.z);
                if (d0 == v) cand = min(cand, 2 * j);
                float c1 = __fmaf_rn(fqz, Br.y,
                           __fmaf_rn(fqy, Ar.w, __fmul_rn(fqx, Ar.y)));
                float d1 = __fadd_rn(__fadd_rn(fqs, c1), Br.w);
                if (d1 == v) cand = min(cand, 2 * j + 1);
            }
            #pragma unroll
            for (int off = 16; off > 0; off >>= 1)
                cand = min(cand, __shfl_xor_sync(0xffffffffu, cand, off));

            if (lane == 0 && (mg0 + q) < N_QUERY) sidx[ql0 + q] = cand;
        }
    }
    __syncthreads();

    // Warp-cooperative coalesced gather: one query row == 32 lanes x float4
    for (int qq = warp; qq < QPB; qq += WARPS) {
        const int m = qbase + qq;
        if (m >= N_QUERY) break;
        const int src = sidx[qq];
        const float4 v = *(const float4*)(features + (size_t)src * FDIM + lane * 4);
        *(float4*)(out + (size_t)m * FDIM + lane * 4) = v;
    }
}

extern "C" void kernel_launch(void* const* d_in, const int* in_sizes, int n_in,
                              void* d_out, int out_size) {
    const float* pts      = (const float*)d_in[0];  // (1, 1024, 32, 3)
    const float* lidar    = (const float*)d_in[1];  // (1, 8192, 3)
    const float* features = (const float*)d_in[2];  // (1, 8192, 128)
    float* out = (float*)d_out;                     // (1, 1024, 32, 128)

    const int smem_bytes = 2 * PAIRS * (int)sizeof(float4);   // 128 KB pair-packed
    cudaFuncSetAttribute(nn_gather_kernel,
                         cudaFuncAttributeMaxDynamicSharedMemorySize, smem_bytes);

    nn_gather_kernel<<<NBLK, THREADS, smem_bytes>>>(pts, lidar, features, out);
}

// round 17
// speedup vs baseline: 1.0390x; 1.0384x over previous
#include <cuda_runtime.h>
#include <cstdint>
#include <cstddef>

// Problem constants (fixed by the benchmark shapes)
#define N_QUERY 32768   // 1024 rays * 32 samples
#define N_LIDAR 8192
#define FDIM    128
#define THREADS 512
#define WARPS   (THREADS / 32)      // 16
#define QPW     7                   // queries per warp-pass
#define PASSES  2                   // 16 warps * 2 passes * 7 = 224 queries/block
#define QPB     (WARPS * QPW * PASSES)          // 224
#define NBLK    ((N_QUERY + QPB - 1) / QPB)     // 147 blocks -> one full wave
#define PAIRS   (N_LIDAR / 2)       // 4096 point-pairs
#define NITER   (PAIRS / 32)        // 128 iterations (one pair per lane)
#define TI      4                   // iterations per tile (256 points/tile)
#define NTILE   (NITER / TI)        // 32 tiles

using u64 = unsigned long long;

// ---- packed f32x2 helpers (sm_103a): bitwise-identical per-half to scalar rn ----
__device__ __forceinline__ u64 pack2(float lo, float hi) {
    u64 r; asm("mov.b64 %0, {%1, %2};" : "=l"(r) : "f"(lo), "f"(hi)); return r;
}
__device__ __forceinline__ u64 dup2(float x) {
    u64 r; asm("mov.b64 %0, {%1, %1};" : "=l"(r) : "f"(x)); return r;
}
__device__ __forceinline__ u64 mul2(u64 a, u64 b) {
    u64 d; asm("mul.rn.f32x2 %0, %1, %2;" : "=l"(d) : "l"(a), "l"(b)); return d;
}
__device__ __forceinline__ u64 fma2(u64 a, u64 b, u64 c) {
    u64 d; asm("fma.rn.f32x2 %0, %1, %2, %3;" : "=l"(d) : "l"(a), "l"(b), "l"(c)); return d;
}
__device__ __forceinline__ u64 add2(u64 a, u64 b) {
    u64 d; asm("add.rn.f32x2 %0, %1, %2;" : "=l"(d) : "l"(a), "l"(b)); return d;
}
__device__ __forceinline__ float2 asf2(u64 v) {
    float2 f; asm("mov.b64 {%0, %1}, %2;" : "=f"(f.x), "=f"(f.y) : "l"(v)); return f;
}

// Monotone bijection float-order -> unsigned-order (ALL floats). Comparison only.
__device__ __forceinline__ unsigned ford(float v) {
    unsigned b = __float_as_uint(v);
    return (b & 0x80000000u) ? ~b : (b | 0x80000000u);
}
__device__ __forceinline__ float funord(unsigned o) {
    return __uint_as_float((o & 0x80000000u) ? (o & 0x7fffffffu) : ~o);
}

__global__ void __launch_bounds__(THREADS, 1)
nn_gather_kernel(const float* __restrict__ pts,
                 const float* __restrict__ lidar,
                 const float* __restrict__ features,
                 float* __restrict__ out)
{
    // Pair-packed, PRE-SCALED lidar: for points 2j, 2j+1
    //   sA[j] = (-2*x0, -2*x1, -2*y0, -2*y1)
    //   sB[j] = (-2*z0, -2*z1,  s0,    s1 )   (s = ||k||^2, unscaled)
    // Scaling by -2 is exact; rn(-2u) = -2*rn(u), so the dot chain below produces
    // exactly -2*cross with the reference's rounding at every step.
    extern __shared__ float4 smem4[];
    float4* sA = smem4;                 // [PAIRS]
    float4* sB = smem4 + PAIRS;         // [PAIRS]
    __shared__ int sidx[QPB];

    const int tid  = threadIdx.x;
    const int lane = tid & 31;
    const int warp = tid >> 5;

    // Cooperative fill; ||k||^2 with stepwise rounding (x^2+y^2)+z^2 on UNSCALED values
    for (int j = tid; j < PAIRS; j += THREADS) {
        float x0 = lidar[6 * j + 0], y0 = lidar[6 * j + 1], z0 = lidar[6 * j + 2];
        float x1 = lidar[6 * j + 3], y1 = lidar[6 * j + 4], z1 = lidar[6 * j + 5];
        float s0 = __fadd_rn(__fadd_rn(__fmul_rn(x0, x0), __fmul_rn(y0, y0)),
                             __fmul_rn(z0, z0));
        float s1 = __fadd_rn(__fadd_rn(__fmul_rn(x1, x1), __fmul_rn(y1, y1)),
                             __fmul_rn(z1, z1));
        sA[j] = make_float4(-2.0f * x0, -2.0f * x1, -2.0f * y0, -2.0f * y1);
        sB[j] = make_float4(-2.0f * z0, -2.0f * z1, s0, s1);
    }
    __syncthreads();

    const float INF = __int_as_float(0x7f800000);
    const int qbase = blockIdx.x * QPB;             // global query base of block

    for (int pass = 0; pass < PASSES; pass++) {
        // This warp-pass owns QPW consecutive queries.
        const int ql0 = (pass * WARPS + warp) * QPW;    // block-local query base
        const int mg0 = qbase + ql0;                    // global query base

        // Duplicated packed query constants (dup2 once per pass — amortized).
        // Tail safety: clamp the load index; results for m >= N_QUERY discarded.
        u64 QXd[QPW], QYd[QPW], QZd[QPW], QSd[QPW];
        #pragma unroll
        for (int q = 0; q < QPW; q++) {
            const int m = min(mg0 + q, N_QUERY - 1);
            float ax = __ldg(pts + 3 * m + 0);
            float ay = __ldg(pts + 3 * m + 1);
            float az = __ldg(pts + 3 * m + 2);
            float as = __fadd_rn(__fadd_rn(__fmul_rn(ax, ax), __fmul_rn(ay, ay)),
                                 __fmul_rn(az, az));
            QXd[q] = dup2(ax); QYd[q] = dup2(ay);
            QZd[q] = dup2(az); QSd[q] = dup2(as);
        }

        float best[QPW];
        int   btile[QPW];
        float tmin[QPW];
        #pragma unroll
        for (int q = 0; q < QPW; q++) { best[q] = INF; btile[q] = 0; tmin[q] = INF; }

        // Software-pipelined scan, last iteration peeled so the prefetch index
        // is unconditional. Lane handles pair i*32+lane; tile = 4 iters.
        const float4* pa = sA + lane;
        const float4* pb = sB + lane;
        float4 A = pa[0];
        float4 B = pb[0];

        #pragma unroll 4
        for (int i = 0; i < NITER - 1; i++) {
            const float4 An = pa[(i + 1) * 32];   // unconditional prefetch
            const float4 Bn = pb[(i + 1) * 32];

            const u64 KX = pack2(A.x, A.y);       // (-2x0, -2x1) — free reg pair
            const u64 KY = pack2(A.z, A.w);       // (-2y0, -2y1)
            const u64 KZ = pack2(B.x, B.y);       // (-2z0, -2z1)
            const u64 KS = pack2(B.z, B.w);       // ( s0,   s1 )

            #pragma unroll
            for (int q = 0; q < QPW; q++) {
                // c' = fma(qz,-2kz, fma(qy,-2ky, rn(qx*-2kx))) == -2*cross, exact
                u64 c = fma2(QZd[q], KZ, fma2(QYd[q], KY, mul2(QXd[q], KX)));
                // d2 = rn( rn(qs + c') + ks )  == rn( rn(qs - 2*cross) + ks )
                u64 d2 = add2(add2(QSd[q], c), KS);
                float2 f = asf2(d2);              // free unpack
                tmin[q] = fminf(tmin[q], fminf(f.x, f.y));
            }

            if ((i & (TI - 1)) == TI - 1) {       // static under unroll 4
                const int t = i >> 2;
                #pragma unroll
                for (int q = 0; q < QPW; q++) {
                    // strict < : keeps the FIRST tile where this lane's min appeared
                    if (tmin[q] < best[q]) { best[q] = tmin[q]; btile[q] = t; }
                    tmin[q] = INF;
                }
            }

            A = An; B = Bn;
        }
        {   // peeled final iteration (i = NITER-1; tile boundary t = NTILE-1)
            const u64 KX = pack2(A.x, A.y);
            const u64 KY = pack2(A.z, A.w);
            const u64 KZ = pack2(B.x, B.y);
            const u64 KS = pack2(B.z, B.w);
            #pragma unroll
            for (int q = 0; q < QPW; q++) {
                u64 c = fma2(QZd[q], KZ, fma2(QYd[q], KY, mul2(QXd[q], KX)));
                u64 d2 = add2(add2(QSd[q], c), KS);
                float2 f = asf2(d2);
                tmin[q] = fminf(tmin[q], fminf(f.x, f.y));
                if (tmin[q] < best[q]) { best[q] = tmin[q]; btile[q] = NTILE - 1; }
            }
        }

        // Epilogue: fused (value, tile) u64 min-reduction per query, then
        // exact first-index recovery in the winning tile.
        for (int q = 0; q < QPW; q++) {
            // key = ord(best)<<32 | tile : min key == min value, earliest tile on ties
            u64 key = ((u64)ford(best[q]) << 32) | (unsigned)btile[q];
            #pragma unroll
            for (int off = 16; off > 0; off >>= 1) {
                u64 other = __shfl_xor_sync(0xffffffffu, key, off);
                key = min(key, other);
            }
            const float v  = funord((unsigned)(key >> 32));
            const int   tl = (int)(unsigned)(key & 0xffffffffu);

            // Reload this query's scalars (uniform) and rescan the winning tile
            // with the same bit-exact sequence on the scaled inputs.
            const int m = min(mg0 + q, N_QUERY - 1);
            const float fqx = __ldg(pts + 3 * m + 0);
            const float fqy = __ldg(pts + 3 * m + 1);
            const float fqz = __ldg(pts + 3 * m + 2);
            const float fqs = __fadd_rn(__fadd_rn(__fmul_rn(fqx, fqx),
                                                  __fmul_rn(fqy, fqy)),
                                        __fmul_rn(fqz, fqz));
            int cand = 0x7fffffff;
            #pragma unroll
            for (int ii = 0; ii < TI; ii++) {
                const int j = (tl * TI + ii) * 32 + lane;   // pair index
                const float4 Ar = sA[j];
                const float4 Br = sB[j];
                float c0 = __fmaf_rn(fqz, Br.x,
                           __fmaf_rn(fqy, Ar.z, __fmul_rn(fqx, Ar.x)));
                float d0 = __fadd_rn(__fadd_rn(fqs, c0), Br.z);
                if (d0 == v) cand = min(cand, 2 * j);
                float c1 = __fmaf_rn(fqz, Br.y,
                           __fmaf_rn(fqy, Ar.w, __fmul_rn(fqx, Ar.y)));
                float d1 = __fadd_rn(__fadd_rn(fqs, c1), Br.w);
                if (d1 == v) cand = min(cand, 2 * j + 1);
            }
            #pragma unroll
            for (int off = 16; off > 0; off >>= 1)
                cand = min(cand, __shfl_xor_sync(0xffffffffu, cand, off));

            if (lane == 0 && (mg0 + q) < N_QUERY) sidx[ql0 + q] = cand;
        }
    }
    __syncthreads();

    // Warp-cooperative coalesced gather: one query row == 32 lanes x float4
    for (int qq = warp; qq < QPB; qq += WARPS) {
        const int m = qbase + qq;
        if (m >= N_QUERY) break;
        const int src = sidx[qq];
        const float4 v = *(const float4*)(features + (size_t)src * FDIM + lane * 4);
        *(float4*)(out + (size_t)m * FDIM + lane * 4) = v;
    }
}

extern "C" void kernel_launch(void* const* d_in, const int* in_sizes, int n_in,
                              void* d_out, int out_size) {
    const float* pts      = (const float*)d_in[0];  // (1, 1024, 32, 3)
    const float* lidar    = (const float*)d_in[1];  // (1, 8192, 3)
    const float* features = (const float*)d_in[2];  // (1, 8192, 128)
    float* out = (float*)d_out;                     // (1, 1024, 32, 128)

    const int smem_bytes = 2 * PAIRS * (int)sizeof(float4);   // 128 KB pair-packed
    cudaFuncSetAttribute(nn_gather_kernel,
                         cudaFuncAttributeMaxDynamicSharedMemorySize, smem_bytes);

    nn_gather_kernel<<<NBLK, THREADS, smem_bytes>>>(pts, lidar, features, out);
}